// round 1
// baseline (speedup 1.0000x reference)
#include <cuda_runtime.h>
#include <math.h>
#include <stdint.h>

#define Bq    32
#define Lq    512
#define Dq    768
#define HIDq  192
#define KKq   5
#define DIq   1536
#define DSq   16
#define DTRq  48
#define DCONVq 4
#define Nq    (Bq*Lq)        // 16384
#define EPSq  1e-5f

// ---------------- scratch (static device allocations; no cudaMalloc) ----------------
__device__ float g_h0  [Nq*HIDq];
__device__ float g_tmpH[Nq*HIDq];
__device__ float g_h2  [Nq*HIDq];
__device__ float g_e   [Nq*Dq];
__device__ float g_x1  [Nq*Dq];
__device__ float g_xn  [Nq*Dq];
__device__ float g_xz  [Nq*2*DIq];     // 3072 wide: xm | z
__device__ float g_xm2 [Nq*DIq];
__device__ float g_dbc [Nq*80];        // dt(48) | B(16) | C(16)
__device__ float g_del [Nq*DIq];
__device__ float g_y   [Nq*DIq];
__device__ float g_mo  [Nq*Dq];
__device__ float g_gl  [Nq*Dq];
__device__ float g_xf  [Nq*Dq];
__device__ float g_rm  [Nq];
__device__ float g_rs  [Nq];
__device__ float g_rm2 [Nq];
__device__ float g_rs2 [Nq];
__device__ float g_sum [Dq];
__device__ float g_sq  [Dq];
__device__ float g_fid [Bq*Dq];

// ---------------- GEMM: C[M,Nc] = A[M,K] (lda) @ W[Nc,K]^T ----------------
// 128x128 block tile, BK=16, 256 threads, 8x8 micro-tile. fp32.
__global__ void __launch_bounds__(256) gemm_nt(
    const float* __restrict__ A, int lda,
    const float* __restrict__ W,
    float* __restrict__ C, int M, int Nc, int K)
{
    __shared__ float As[16][132];
    __shared__ float Ws[16][132];
    const int bm = blockIdx.y * 128;
    const int bn = blockIdx.x * 128;
    const int t  = threadIdx.x;
    const int lk = t & 15;
    const int lr = t >> 4;            // 0..15
    const int tm = (t >> 4) << 3;     // 0..120
    const int tn = (t & 15) << 3;

    float acc[8][8];
    #pragma unroll
    for (int i = 0; i < 8; i++)
        #pragma unroll
        for (int j = 0; j < 8; j++) acc[i][j] = 0.f;

    for (int k0 = 0; k0 < K; k0 += 16) {
        #pragma unroll
        for (int i = 0; i < 8; i++) {
            int r = lr + i*16;
            As[lk][r] = A[(size_t)(bm + r)*lda + (k0 + lk)];
            int j = bn + r;
            Ws[lk][r] = (j < Nc) ? W[(size_t)j*K + (k0 + lk)] : 0.f;
        }
        __syncthreads();
        #pragma unroll
        for (int k = 0; k < 16; k++) {
            float a[8], b[8];
            *(float4*)&a[0] = *(const float4*)&As[k][tm];
            *(float4*)&a[4] = *(const float4*)&As[k][tm+4];
            *(float4*)&b[0] = *(const float4*)&Ws[k][tn];
            *(float4*)&b[4] = *(const float4*)&Ws[k][tn+4];
            #pragma unroll
            for (int i = 0; i < 8; i++)
                #pragma unroll
                for (int j = 0; j < 8; j++)
                    acc[i][j] = fmaf(a[i], b[j], acc[i][j]);
        }
        __syncthreads();
    }
    #pragma unroll
    for (int i = 0; i < 8; i++) {
        int r = bm + tm + i;
        #pragma unroll
        for (int j = 0; j < 8; j++) {
            int c = bn + tn + j;
            if (c < Nc) C[(size_t)r*Nc + c] = acc[i][j];
        }
    }
}

// ---------------- BatchNorm stats over all rows (axes 0,1), per channel ----------------
// grid (32, ceil(C/256)), block 256. sum/sq must be zeroed first.
__global__ void bn_stats(const float* __restrict__ X, int M, int C,
                         float* __restrict__ sum, float* __restrict__ sq)
{
    int c = blockIdx.y * blockDim.x + threadIdx.x;
    if (c >= C) return;
    int rows = M / gridDim.x;
    int r0 = blockIdx.x * rows;
    float s = 0.f, ss = 0.f;
    for (int r = r0; r < r0 + rows; r++) {
        float v = X[(size_t)r*C + c];
        s += v; ss += v*v;
    }
    atomicAdd(&sum[c], s);
    atomicAdd(&sq[c],  ss);
}

// Y = silu(bn(X))
__global__ void bn_silu(const float* __restrict__ X, float* __restrict__ Y,
                        const float* __restrict__ sum, const float* __restrict__ sq,
                        const float* __restrict__ g, const float* __restrict__ b,
                        int M, int C)
{
    int idx = blockIdx.x * blockDim.x + threadIdx.x;
    if (idx >= M*C) return;
    int c = idx % C;
    float mean = sum[c] / (float)M;
    float var  = sq[c] / (float)M - mean*mean;
    float v = (X[idx] - mean) * rsqrtf(var + EPSq) * g[c] + b[c];
    Y[idx] = v / (1.f + expf(-v));
}

// Y = res + bn(X)
__global__ void bn_add(const float* __restrict__ X, const float* __restrict__ res,
                       float* __restrict__ Y,
                       const float* __restrict__ sum, const float* __restrict__ sq,
                       const float* __restrict__ g, const float* __restrict__ b,
                       int M, int C)
{
    int idx = blockIdx.x * blockDim.x + threadIdx.x;
    if (idx >= M*C) return;
    int c = idx % C;
    float mean = sum[c] / (float)M;
    float var  = sq[c] / (float)M - mean*mean;
    Y[idx] = res[idx] + (X[idx] - mean) * rsqrtf(var + EPSq) * g[c] + b[c];
}

// ---------------- depthwise conv K=5, same padding (pad 2) ----------------
__global__ void dwconv5(const float* __restrict__ X, const float* __restrict__ w,
                        float* __restrict__ Y)
{
    int idx = blockIdx.x * blockDim.x + threadIdx.x;
    if (idx >= Nq*HIDq) return;
    int c  = idx % HIDq;
    int l  = (idx / HIDq) % Lq;
    int bb = idx / (HIDq*Lq);
    const float* xb = X + (size_t)bb*Lq*HIDq;
    float acc = 0.f;
    #pragma unroll
    for (int k = 0; k < 5; k++) {
        int ls = l - 2 + k;
        if (ls >= 0 && ls < Lq) acc += xb[(size_t)ls*HIDq + c] * w[c*5 + k];
    }
    Y[idx] = acc;
}

// ---------------- causal depthwise conv K=4 (pad 3,0) + bias + silu ----------------
// reads xm from XZ (row stride 3072, cols [0,1536))
__global__ void conv_causal_silu(const float* __restrict__ XZ, const float* __restrict__ w,
                                 const float* __restrict__ bias, float* __restrict__ Y)
{
    int idx = blockIdx.x * blockDim.x + threadIdx.x;
    if (idx >= Nq*DIq) return;
    int c  = idx % DIq;
    int l  = (idx / DIq) % Lq;
    int bb = idx / (DIq*Lq);
    float acc = bias[c];
    #pragma unroll
    for (int k = 0; k < 4; k++) {
        int ls = l - 3 + k;
        if (ls >= 0) acc += XZ[(size_t)(bb*Lq + ls)*(2*DIq) + c] * w[c*4 + k];
    }
    Y[idx] = acc / (1.f + expf(-acc));
}

// ---------------- rowwise LN stats over last dim (C=768) ----------------
__global__ void row_stats(const float* __restrict__ X, float* __restrict__ mean,
                          float* __restrict__ rstd, int C)
{
    int row = blockIdx.x;
    const float* xr = X + (size_t)row*C;
    float s = 0.f, ss = 0.f;
    for (int c = threadIdx.x; c < C; c += blockDim.x) {
        float v = xr[c]; s += v; ss += v*v;
    }
    __shared__ float sh1[32], sh2[32];
    for (int o = 16; o; o >>= 1) {
        s  += __shfl_down_sync(0xffffffffu, s, o);
        ss += __shfl_down_sync(0xffffffffu, ss, o);
    }
    int lane = threadIdx.x & 31, warp = threadIdx.x >> 5;
    if (lane == 0) { sh1[warp] = s; sh2[warp] = ss; }
    __syncthreads();
    if (threadIdx.x < 8) {
        s = sh1[threadIdx.x]; ss = sh2[threadIdx.x];
        for (int o = 4; o; o >>= 1) {
            s  += __shfl_down_sync(0xffu, s, o);
            ss += __shfl_down_sync(0xffu, ss, o);
        }
        if (threadIdx.x == 0) {
            float m = s / (float)C;
            float v = ss / (float)C - m*m;
            mean[row] = m;
            rstd[row] = rsqrtf(v + EPSq);
        }
    }
}

// xn = (x1 - m)*rs*g + b
__global__ void ln_apply(const float* __restrict__ X, const float* __restrict__ mean,
                         const float* __restrict__ rstd, const float* __restrict__ g,
                         const float* __restrict__ b, float* __restrict__ Y, int C)
{
    int idx = blockIdx.x * blockDim.x + threadIdx.x;
    if (idx >= Nq*C) return;
    int row = idx / C, c = idx % C;
    Y[idx] = (X[idx] - mean[row]) * rstd[row] * g[c] + b[c];
}

// feat_attr[b,c] = max_l LN(x1)[b,l,c]
__global__ void attr_max(const float* __restrict__ X, const float* __restrict__ mean,
                         const float* __restrict__ rstd, const float* __restrict__ g,
                         const float* __restrict__ b, float* __restrict__ out)
{
    int c  = blockIdx.y * blockDim.x + threadIdx.x;
    int bb = blockIdx.x;
    float gm = g[c], gb = b[c];
    float mx = -3.4e38f;
    for (int l = 0; l < Lq; l++) {
        int row = bb*Lq + l;
        float v = (X[(size_t)row*Dq + c] - mean[row]) * rstd[row] * gm + gb;
        mx = fmaxf(mx, v);
    }
    out[bb*Dq + c] = mx;
}

// delta = softplus(delta_raw + bias)
__global__ void softplus_bias(float* __restrict__ X, const float* __restrict__ bias)
{
    int idx = blockIdx.x * blockDim.x + threadIdx.x;
    if (idx >= Nq*DIq) return;
    float v = X[idx] + bias[idx % DIq];
    X[idx] = (v > 20.f) ? v : log1pf(expf(v));
}

// ---------------- selective scan ----------------
// one thread per (b,d); B/C tiles staged in smem per 128-step chunk
__global__ void __launch_bounds__(256) scan_k(
    const float* __restrict__ delta, const float* __restrict__ u,
    const float* __restrict__ dbc,   const float* __restrict__ xz,
    const float* __restrict__ A_log, const float* __restrict__ Dp,
    float* __restrict__ y)
{
    __shared__ float Bs[128][DSq];
    __shared__ float Cs[128][DSq];
    const int bb = blockIdx.y;
    const int d  = blockIdx.x * 256 + threadIdx.x;

    float A[DSq], h[DSq];
    #pragma unroll
    for (int s = 0; s < DSq; s++) { A[s] = -expf(A_log[d*DSq + s]); h[s] = 0.f; }
    const float dp = Dp[d];

    for (int c0 = 0; c0 < Lq; c0 += 128) {
        for (int i = threadIdx.x; i < 128*DSq; i += 256) {
            int l = i >> 4, s = i & 15;
            size_t row = (size_t)(bb*Lq + c0 + l);
            Bs[l][s] = dbc[row*80 + DTRq + s];
            Cs[l][s] = dbc[row*80 + DTRq + DSq + s];
        }
        __syncthreads();
        for (int l = 0; l < 128; l++) {
            size_t row = (size_t)(bb*Lq + c0 + l);
            float dv = delta[row*DIq + d];
            float uv = u[row*DIq + d];
            float du = dv * uv;
            float acc = 0.f;
            #pragma unroll
            for (int s = 0; s < DSq; s++) {
                h[s] = h[s] * __expf(dv * A[s]) + du * Bs[l][s];
                acc  = fmaf(h[s], Cs[l][s], acc);
            }
            float zv = xz[row*(2*DIq) + DIq + d];
            float sz = zv / (1.f + __expf(-zv));
            y[row*DIq + d] = (acc + uv*dp) * sz;
        }
        __syncthreads();
    }
}

// xf = x1 + mo*sigmoid(gl + gate_b) + x
__global__ void combine(const float* __restrict__ x, const float* __restrict__ x1,
                        const float* __restrict__ mo, const float* __restrict__ gl,
                        const float* __restrict__ gb, float* __restrict__ xf)
{
    int idx = blockIdx.x * blockDim.x + threadIdx.x;
    if (idx >= Nq*Dq) return;
    int c = idx % Dq;
    float gate = 1.f / (1.f + expf(-(gl[idx] + gb[c])));
    xf[idx] = x1[idx] + mo[idx]*gate + x[idx];
}

// feat_id[b,c] = mean_l LN(xf)[b,l,c]
__global__ void feat_id_k(const float* __restrict__ X, const float* __restrict__ mean,
                          const float* __restrict__ rstd, const float* __restrict__ g,
                          const float* __restrict__ b, float* __restrict__ fid,
                          float* __restrict__ out)
{
    int c  = blockIdx.y * blockDim.x + threadIdx.x;
    int bb = blockIdx.x;
    float gm = g[c], gb = b[c];
    float s = 0.f;
    for (int l = 0; l < Lq; l++) {
        int row = bb*Lq + l;
        s += (X[(size_t)row*Dq + c] - mean[row]) * rstd[row] * gm + gb;
    }
    float v = s / (float)Lq;
    fid[bb*Dq + c] = v;
    out[bb*Dq + c] = v;
}

// feat_id_bn: BN over batch axis only
__global__ void feat_bn(const float* __restrict__ fid, const float* __restrict__ g,
                        const float* __restrict__ b, float* __restrict__ out)
{
    int c = blockIdx.x * blockDim.x + threadIdx.x;
    if (c >= Dq) return;
    float s = 0.f, ss = 0.f;
    for (int bb = 0; bb < Bq; bb++) {
        float v = fid[bb*Dq + c]; s += v; ss += v*v;
    }
    float m = s / (float)Bq;
    float var = ss / (float)Bq - m*m;
    float rs = rsqrtf(var + EPSq);
    for (int bb = 0; bb < Bq; bb++)
        out[bb*Dq + c] = (fid[bb*Dq + c] - m) * rs * g[c] + b[c];
}

// ---------------- host ----------------
#define GETSYM(p, s) { void* _t; cudaGetSymbolAddress(&_t, s); p = (float*)_t; }

extern "C" void kernel_launch(void* const* d_in, const int* in_sizes, int n_in,
                              void* d_out, int out_size)
{
    const float* x        = (const float*)d_in[0];
    const float* sq_w     = (const float*)d_in[1];
    const float* sq_bn_g  = (const float*)d_in[2];
    const float* sq_bn_b  = (const float*)d_in[3];
    const float* dw_w     = (const float*)d_in[4];
    const float* dw_bn_g  = (const float*)d_in[5];
    const float* dw_bn_b  = (const float*)d_in[6];
    const float* ex_w     = (const float*)d_in[7];
    const float* ex_bn_g  = (const float*)d_in[8];
    const float* ex_bn_b  = (const float*)d_in[9];
    const float* attr_g   = (const float*)d_in[10];
    const float* attr_b   = (const float*)d_in[11];
    const float* mnorm_g  = (const float*)d_in[12];
    const float* mnorm_b  = (const float*)d_in[13];
    const float* in_proj_w= (const float*)d_in[14];
    const float* conv_w   = (const float*)d_in[15];
    const float* conv_b   = (const float*)d_in[16];
    const float* xproj_w  = (const float*)d_in[17];
    const float* dtproj_w = (const float*)d_in[18];
    const float* dtproj_b = (const float*)d_in[19];
    const float* A_log    = (const float*)d_in[20];
    const float* D_param  = (const float*)d_in[21];
    const float* out_proj_w = (const float*)d_in[22];
    const float* gate_w   = (const float*)d_in[23];
    const float* gate_b   = (const float*)d_in[24];
    const float* idn_g    = (const float*)d_in[25];
    const float* idn_b    = (const float*)d_in[26];
    const float* idbn_g   = (const float*)d_in[27];
    const float* idbn_b   = (const float*)d_in[28];
    float* out = (float*)d_out;

    float *h0,*tmpH,*h2,*e,*x1,*xn,*xz,*xm2,*dbc,*del,*y,*mo,*gl,*xf;
    float *rm,*rs,*rm2,*rs2,*sum,*sq,*fid;
    GETSYM(h0, g_h0);   GETSYM(tmpH, g_tmpH); GETSYM(h2, g_h2);
    GETSYM(e, g_e);     GETSYM(x1, g_x1);     GETSYM(xn, g_xn);
    GETSYM(xz, g_xz);   GETSYM(xm2, g_xm2);   GETSYM(dbc, g_dbc);
    GETSYM(del, g_del); GETSYM(y, g_y);       GETSYM(mo, g_mo);
    GETSYM(gl, g_gl);   GETSYM(xf, g_xf);
    GETSYM(rm, g_rm);   GETSYM(rs, g_rs);     GETSYM(rm2, g_rm2); GETSYM(rs2, g_rs2);
    GETSYM(sum, g_sum); GETSYM(sq, g_sq);     GETSYM(fid, g_fid);

    const int T = 256;
    dim3 gHID((Nq*HIDq + T-1)/T), gD((Nq*Dq + T-1)/T), gDI((Nq*DIq + T-1)/T);

    // 1) squeeze: h0 = x @ sq_w^T ; BN+SiLU
    gemm_nt<<<dim3((HIDq+127)/128, Nq/128), T>>>(x, Dq, sq_w, h0, Nq, HIDq, Dq);
    cudaMemsetAsync(sum, 0, HIDq*sizeof(float));
    cudaMemsetAsync(sq,  0, HIDq*sizeof(float));
    bn_stats<<<dim3(32,1), T>>>(h0, Nq, HIDq, sum, sq);
    bn_silu<<<gHID, T>>>(h0, h0, sum, sq, sq_bn_g, sq_bn_b, Nq, HIDq);

    // 2) dwconv K=5 ; BN+SiLU
    dwconv5<<<gHID, T>>>(h0, dw_w, tmpH);
    cudaMemsetAsync(sum, 0, HIDq*sizeof(float));
    cudaMemsetAsync(sq,  0, HIDq*sizeof(float));
    bn_stats<<<dim3(32,1), T>>>(tmpH, Nq, HIDq, sum, sq);
    bn_silu<<<gHID, T>>>(tmpH, h2, sum, sq, dw_bn_g, dw_bn_b, Nq, HIDq);

    // 3) excite: e = h2 @ ex_w^T ; x1 = x + BN(e)
    gemm_nt<<<dim3(Dq/128, Nq/128), T>>>(h2, HIDq, ex_w, e, Nq, Dq, HIDq);
    cudaMemsetAsync(sum, 0, Dq*sizeof(float));
    cudaMemsetAsync(sq,  0, Dq*sizeof(float));
    bn_stats<<<dim3(32,3), T>>>(e, Nq, Dq, sum, sq);
    bn_add<<<gD, T>>>(e, x, x1, sum, sq, ex_bn_g, ex_bn_b, Nq, Dq);

    // 4) LN stats of x1; feat_attr; xn
    row_stats<<<Nq, T>>>(x1, rm, rs, Dq);
    attr_max<<<dim3(Bq,3), T>>>(x1, rm, rs, attr_g, attr_b, out);
    ln_apply<<<gD, T>>>(x1, rm, rs, mnorm_g, mnorm_b, xn, Dq);

    // 5) Mamba in_proj
    gemm_nt<<<dim3(2*DIq/128, Nq/128), T>>>(xn, Dq, in_proj_w, xz, Nq, 2*DIq, Dq);

    // 6) causal conv + silu -> xm2
    conv_causal_silu<<<gDI, T>>>(xz, conv_w, conv_b, xm2);

    // 7) x_proj -> dbc ; dt_proj -> delta ; softplus
    gemm_nt<<<dim3(1, Nq/128), T>>>(xm2, DIq, xproj_w, dbc, Nq, 80, DIq);
    gemm_nt<<<dim3(DIq/128, Nq/128), T>>>(dbc, 80, dtproj_w, del, Nq, DIq, DTRq);
    softplus_bias<<<gDI, T>>>(del, dtproj_b);

    // 8) selective scan (fused +u*D and *silu(z))
    scan_k<<<dim3(DIq/256, Bq), 256>>>(del, xm2, dbc, xz, A_log, D_param, y);

    // 9) out_proj, gate, combine
    gemm_nt<<<dim3(Dq/128, Nq/128), T>>>(y, DIq, out_proj_w, mo, Nq, Dq, DIq);
    gemm_nt<<<dim3(Dq/128, Nq/128), T>>>(xn, Dq, gate_w, gl, Nq, Dq, Dq);
    combine<<<gD, T>>>(x, x1, mo, gl, gate_b, xf);

    // 10) feat_id + feat_id_bn
    row_stats<<<Nq, T>>>(xf, rm2, rs2, Dq);
    feat_id_k<<<dim3(Bq,3), T>>>(xf, rm2, rs2, idn_g, idn_b, fid, out + Bq*Dq);
    feat_bn<<<3, T>>>(fid, idbn_g, idbn_b, out + 2*Bq*Dq);
}

// round 4
// speedup vs baseline: 2.6233x; 2.6233x over previous
#include <cuda_runtime.h>
#include <math.h>
#include <stdint.h>

#define Bq    32
#define Lq    512
#define Dq    768
#define HIDq  192
#define DIq   1536
#define DSq   16
#define DTRq  48
#define Nq    (Bq*Lq)        // 16384
#define EPSq  1e-5f

// ---------------- scratch (static device allocations; no cudaMalloc) ----------------
__device__ __align__(256) float g_h0  [Nq*HIDq];
__device__ __align__(256) float g_tmpH[Nq*HIDq];
__device__ __align__(256) float g_h2  [Nq*HIDq];
__device__ __align__(256) float g_e   [Nq*Dq];
__device__ __align__(256) float g_x1  [Nq*Dq];
__device__ __align__(256) float g_xn  [Nq*Dq];
__device__ __align__(256) float g_xz  [Nq*2*DIq];     // 3072 wide: xm | z
__device__ __align__(256) float g_xm2 [Nq*DIq];
__device__ __align__(256) float g_dbc [Nq*80];        // dt(48) | B(16) | C(16)
__device__ __align__(256) float g_del [Nq*DIq];
__device__ __align__(256) float g_y   [Nq*DIq];
__device__ __align__(256) float g_mo  [Nq*Dq];
__device__ __align__(256) float g_gl  [Nq*Dq];
__device__ __align__(256) float g_xf  [Nq*Dq];
__device__ __align__(256) float g_rm  [Nq];
__device__ __align__(256) float g_rs  [Nq];
__device__ __align__(256) float g_rm2 [Nq];
__device__ __align__(256) float g_rs2 [Nq];
__device__ __align__(256) float g_sum [Dq];
__device__ __align__(256) float g_sq  [Dq];
__device__ __align__(256) float g_fid [Bq*Dq];

// ================= TF32 mma.sync GEMM (sm_80+ path; works on plain sm_103) =========
// C[M,Nc] = A[M,K](lda) @ W[Nc,K]^T.  BM=128, BN=128, BK=32.
// 8 warps = 4(M) x 2(N); warp tile 32x64; mma.m16n8k8.tf32.
#define SA 36   // smem row stride (floats), padded: conflict-free for frag loads

__device__ __forceinline__ uint32_t f2tf(float f) {
    uint32_t u;
    asm("cvt.rna.tf32.f32 %0, %1;" : "=r"(u) : "f"(f));
    return u;
}

__device__ __forceinline__ void mma_tf32(float* d, const uint32_t* a, const uint32_t* b) {
    asm volatile(
        "mma.sync.aligned.m16n8k8.row.col.f32.tf32.tf32.f32 "
        "{%0,%1,%2,%3}, {%4,%5,%6,%7}, {%8,%9}, {%0,%1,%2,%3};"
        : "+f"(d[0]), "+f"(d[1]), "+f"(d[2]), "+f"(d[3])
        : "r"(a[0]), "r"(a[1]), "r"(a[2]), "r"(a[3]), "r"(b[0]), "r"(b[1]));
}

__global__ void __launch_bounds__(256) gemm_tc(
    const float* __restrict__ A, int lda,
    const float* __restrict__ W,
    float* __restrict__ C, int Nc, int K)
{
    __shared__ uint32_t As[128*SA];
    __shared__ uint32_t Bs[128*SA];

    const int bm = blockIdx.y * 128;
    const int bn = blockIdx.x * 128;
    const int t  = threadIdx.x;
    const int wid  = t >> 5;
    const int lane = t & 31;
    const int qr = lane >> 2;   // 0..7
    const int qc = lane & 3;    // 0..3
    const int warp_m = wid & 3;       // 0..3 -> 32-row band
    const int warp_n = wid >> 2;      // 0..1 -> 64-col band

    float acc[2][8][4];
    #pragma unroll
    for (int mt = 0; mt < 2; mt++)
        #pragma unroll
        for (int nt = 0; nt < 8; nt++)
            #pragma unroll
            for (int q = 0; q < 4; q++) acc[mt][nt][q] = 0.f;

    const int NC = (K + 31) / 32;

    float4 aReg[4], bReg[4];
    const float4 z4 = make_float4(0.f, 0.f, 0.f, 0.f);

    // prologue: stage chunk 0 into registers
    {
        const int k0 = 0;
        #pragma unroll
        for (int i = 0; i < 4; i++) {
            int idx = t + i*256;
            int r = idx >> 3;
            int c4 = (idx & 7) * 4;
            aReg[i] = (k0 + c4 < K) ? *(const float4*)&A[(size_t)(bm + r)*lda + k0 + c4] : z4;
            int j = bn + r;
            bReg[i] = (j < Nc && k0 + c4 < K) ? *(const float4*)&W[(size_t)j*K + k0 + c4] : z4;
        }
    }

    for (int ch = 0; ch < NC; ch++) {
        __syncthreads();   // previous chunk's frag reads done
        // store staged regs to smem with tf32 rounding
        #pragma unroll
        for (int i = 0; i < 4; i++) {
            int idx = t + i*256;
            int r = idx >> 3;
            int c4 = (idx & 7) * 4;
            uint4 ua = make_uint4(f2tf(aReg[i].x), f2tf(aReg[i].y), f2tf(aReg[i].z), f2tf(aReg[i].w));
            uint4 ub = make_uint4(f2tf(bReg[i].x), f2tf(bReg[i].y), f2tf(bReg[i].z), f2tf(bReg[i].w));
            *(uint4*)&As[r*SA + c4] = ua;
            *(uint4*)&Bs[r*SA + c4] = ub;
        }
        __syncthreads();

        // issue next chunk's global loads early (hidden behind MMA)
        if (ch + 1 < NC) {
            const int k0 = (ch + 1) * 32;
            #pragma unroll
            for (int i = 0; i < 4; i++) {
                int idx = t + i*256;
                int r = idx >> 3;
                int c4 = (idx & 7) * 4;
                aReg[i] = (k0 + c4 < K) ? *(const float4*)&A[(size_t)(bm + r)*lda + k0 + c4] : z4;
                int j = bn + r;
                bReg[i] = (j < Nc && k0 + c4 < K) ? *(const float4*)&W[(size_t)j*K + k0 + c4] : z4;
            }
        }

        // MMA over the 32-wide K chunk, 4 k-steps of 8
        #pragma unroll
        for (int ks = 0; ks < 4; ks++) {
            const int k0 = ks * 8;
            uint32_t afr[2][4];
            #pragma unroll
            for (int mt = 0; mt < 2; mt++) {
                int r0 = warp_m*32 + mt*16 + qr;
                afr[mt][0] = As[r0*SA + k0 + qc];
                afr[mt][1] = As[(r0+8)*SA + k0 + qc];
                afr[mt][2] = As[r0*SA + k0 + qc + 4];
                afr[mt][3] = As[(r0+8)*SA + k0 + qc + 4];
            }
            uint32_t bfr[8][2];
            #pragma unroll
            for (int nt = 0; nt < 8; nt++) {
                int n = warp_n*64 + nt*8 + qr;
                bfr[nt][0] = Bs[n*SA + k0 + qc];
                bfr[nt][1] = Bs[n*SA + k0 + qc + 4];
            }
            #pragma unroll
            for (int mt = 0; mt < 2; mt++)
                #pragma unroll
                for (int nt = 0; nt < 8; nt++)
                    mma_tf32(acc[mt][nt], afr[mt], bfr[nt]);
        }
    }

    // epilogue
    #pragma unroll
    for (int mt = 0; mt < 2; mt++) {
        int r0 = bm + warp_m*32 + mt*16 + qr;
        #pragma unroll
        for (int nt = 0; nt < 8; nt++) {
            int c = bn + warp_n*64 + nt*8 + qc*2;
            if (c < Nc) {
                *(float2*)&C[(size_t)r0*Nc + c]     = make_float2(acc[mt][nt][0], acc[mt][nt][1]);
                *(float2*)&C[(size_t)(r0+8)*Nc + c] = make_float2(acc[mt][nt][2], acc[mt][nt][3]);
            }
        }
    }
}

// ---------------- BatchNorm stats over all rows (axes 0,1), per channel ----------------
__global__ void bn_stats(const float* __restrict__ X, int M, int C,
                         float* __restrict__ sum, float* __restrict__ sq)
{
    int c = blockIdx.y * blockDim.x + threadIdx.x;
    if (c >= C) return;
    int rows = M / gridDim.x;
    int r0 = blockIdx.x * rows;
    float s = 0.f, ss = 0.f;
    for (int r = r0; r < r0 + rows; r++) {
        float v = X[(size_t)r*C + c];
        s += v; ss += v*v;
    }
    atomicAdd(&sum[c], s);
    atomicAdd(&sq[c],  ss);
}

__global__ void bn_silu(const float* __restrict__ X, float* __restrict__ Y,
                        const float* __restrict__ sum, const float* __restrict__ sq,
                        const float* __restrict__ g, const float* __restrict__ b,
                        int M, int C)
{
    int idx = blockIdx.x * blockDim.x + threadIdx.x;
    if (idx >= M*C) return;
    int c = idx % C;
    float mean = sum[c] / (float)M;
    float var  = sq[c] / (float)M - mean*mean;
    float v = (X[idx] - mean) * rsqrtf(var + EPSq) * g[c] + b[c];
    Y[idx] = v / (1.f + expf(-v));
}

__global__ void bn_add(const float* __restrict__ X, const float* __restrict__ res,
                       float* __restrict__ Y,
                       const float* __restrict__ sum, const float* __restrict__ sq,
                       const float* __restrict__ g, const float* __restrict__ b,
                       int M, int C)
{
    int idx = blockIdx.x * blockDim.x + threadIdx.x;
    if (idx >= M*C) return;
    int c = idx % C;
    float mean = sum[c] / (float)M;
    float var  = sq[c] / (float)M - mean*mean;
    Y[idx] = res[idx] + (X[idx] - mean) * rsqrtf(var + EPSq) * g[c] + b[c];
}

// ---------------- depthwise conv K=5, same padding ----------------
__global__ void dwconv5(const float* __restrict__ X, const float* __restrict__ w,
                        float* __restrict__ Y)
{
    int idx = blockIdx.x * blockDim.x + threadIdx.x;
    if (idx >= Nq*HIDq) return;
    int c  = idx % HIDq;
    int l  = (idx / HIDq) % Lq;
    int bb = idx / (HIDq*Lq);
    const float* xb = X + (size_t)bb*Lq*HIDq;
    float acc = 0.f;
    #pragma unroll
    for (int k = 0; k < 5; k++) {
        int ls = l - 2 + k;
        if (ls >= 0 && ls < Lq) acc += xb[(size_t)ls*HIDq + c] * w[c*5 + k];
    }
    Y[idx] = acc;
}

// ---------------- causal depthwise conv K=4 + bias + silu ----------------
__global__ void conv_causal_silu(const float* __restrict__ XZ, const float* __restrict__ w,
                                 const float* __restrict__ bias, float* __restrict__ Y)
{
    int idx = blockIdx.x * blockDim.x + threadIdx.x;
    if (idx >= Nq*DIq) return;
    int c  = idx % DIq;
    int l  = (idx / DIq) % Lq;
    int bb = idx / (DIq*Lq);
    float acc = bias[c];
    #pragma unroll
    for (int k = 0; k < 4; k++) {
        int ls = l - 3 + k;
        if (ls >= 0) acc += XZ[(size_t)(bb*Lq + ls)*(2*DIq) + c] * w[c*4 + k];
    }
    Y[idx] = acc / (1.f + expf(-acc));
}

// ---------------- rowwise LN stats ----------------
__global__ void row_stats(const float* __restrict__ X, float* __restrict__ mean,
                          float* __restrict__ rstd, int C)
{
    int row = blockIdx.x;
    const float* xr = X + (size_t)row*C;
    float s = 0.f, ss = 0.f;
    for (int c = threadIdx.x; c < C; c += blockDim.x) {
        float v = xr[c]; s += v; ss += v*v;
    }
    __shared__ float sh1[32], sh2[32];
    for (int o = 16; o; o >>= 1) {
        s  += __shfl_down_sync(0xffffffffu, s, o);
        ss += __shfl_down_sync(0xffffffffu, ss, o);
    }
    int lane = threadIdx.x & 31, warp = threadIdx.x >> 5;
    if (lane == 0) { sh1[warp] = s; sh2[warp] = ss; }
    __syncthreads();
    if (threadIdx.x < 8) {
        s = sh1[threadIdx.x]; ss = sh2[threadIdx.x];
        for (int o = 4; o; o >>= 1) {
            s  += __shfl_down_sync(0xffu, s, o);
            ss += __shfl_down_sync(0xffu, ss, o);
        }
        if (threadIdx.x == 0) {
            float m = s / (float)C;
            float v = ss / (float)C - m*m;
            mean[row] = m;
            rstd[row] = rsqrtf(v + EPSq);
        }
    }
}

__global__ void ln_apply(const float* __restrict__ X, const float* __restrict__ mean,
                         const float* __restrict__ rstd, const float* __restrict__ g,
                         const float* __restrict__ b, float* __restrict__ Y, int C)
{
    int idx = blockIdx.x * blockDim.x + threadIdx.x;
    if (idx >= Nq*C) return;
    int row = idx / C, c = idx % C;
    Y[idx] = (X[idx] - mean[row]) * rstd[row] * g[c] + b[c];
}

__global__ void attr_max(const float* __restrict__ X, const float* __restrict__ mean,
                         const float* __restrict__ rstd, const float* __restrict__ g,
                         const float* __restrict__ b, float* __restrict__ out)
{
    int c  = blockIdx.y * blockDim.x + threadIdx.x;
    int bb = blockIdx.x;
    float gm = g[c], gb = b[c];
    float mx = -3.4e38f;
    for (int l = 0; l < Lq; l++) {
        int row = bb*Lq + l;
        float v = (X[(size_t)row*Dq + c] - mean[row]) * rstd[row] * gm + gb;
        mx = fmaxf(mx, v);
    }
    out[bb*Dq + c] = mx;
}

__global__ void softplus_bias(float* __restrict__ X, const float* __restrict__ bias)
{
    int idx = blockIdx.x * blockDim.x + threadIdx.x;
    if (idx >= Nq*DIq) return;
    float v = X[idx] + bias[idx % DIq];
    X[idx] = (v > 20.f) ? v : log1pf(expf(v));
}

// ---------------- selective scan ----------------
__global__ void __launch_bounds__(256) scan_k(
    const float* __restrict__ delta, const float* __restrict__ u,
    const float* __restrict__ dbc,   const float* __restrict__ xz,
    const float* __restrict__ A_log, const float* __restrict__ Dp,
    float* __restrict__ y)
{
    __shared__ float Bs[128][DSq];
    __shared__ float Cs[128][DSq];
    const int bb = blockIdx.y;
    const int d  = blockIdx.x * 256 + threadIdx.x;

    float A[DSq], h[DSq];
    #pragma unroll
    for (int s = 0; s < DSq; s++) { A[s] = -expf(A_log[d*DSq + s]); h[s] = 0.f; }
    const float dp = Dp[d];

    for (int c0 = 0; c0 < Lq; c0 += 128) {
        for (int i = threadIdx.x; i < 128*DSq; i += 256) {
            int l = i >> 4, s = i & 15;
            size_t row = (size_t)(bb*Lq + c0 + l);
            Bs[l][s] = dbc[row*80 + DTRq + s];
            Cs[l][s] = dbc[row*80 + DTRq + DSq + s];
        }
        __syncthreads();
        for (int l = 0; l < 128; l++) {
            size_t row = (size_t)(bb*Lq + c0 + l);
            float dv = delta[row*DIq + d];
            float uv = u[row*DIq + d];
            float du = dv * uv;
            float acc = 0.f;
            #pragma unroll
            for (int s = 0; s < DSq; s++) {
                h[s] = h[s] * __expf(dv * A[s]) + du * Bs[l][s];
                acc  = fmaf(h[s], Cs[l][s], acc);
            }
            float zv = xz[row*(2*DIq) + DIq + d];
            float sz = zv / (1.f + __expf(-zv));
            y[row*DIq + d] = (acc + uv*dp) * sz;
        }
        __syncthreads();
    }
}

__global__ void combine(const float* __restrict__ x, const float* __restrict__ x1,
                        const float* __restrict__ mo, const float* __restrict__ gl,
                        const float* __restrict__ gb, float* __restrict__ xf)
{
    int idx = blockIdx.x * blockDim.x + threadIdx.x;
    if (idx >= Nq*Dq) return;
    int c = idx % Dq;
    float gate = 1.f / (1.f + expf(-(gl[idx] + gb[c])));
    xf[idx] = x1[idx] + mo[idx]*gate + x[idx];
}

__global__ void feat_id_k(const float* __restrict__ X, const float* __restrict__ mean,
                          const float* __restrict__ rstd, const float* __restrict__ g,
                          const float* __restrict__ b, float* __restrict__ fid,
                          float* __restrict__ out)
{
    int c  = blockIdx.y * blockDim.x + threadIdx.x;
    int bb = blockIdx.x;
    float gm = g[c], gb = b[c];
    float s = 0.f;
    for (int l = 0; l < Lq; l++) {
        int row = bb*Lq + l;
        s += (X[(size_t)row*Dq + c] - mean[row]) * rstd[row] * gm + gb;
    }
    float v = s / (float)Lq;
    fid[bb*Dq + c] = v;
    out[bb*Dq + c] = v;
}

__global__ void feat_bn(const float* __restrict__ fid, const float* __restrict__ g,
                        const float* __restrict__ b, float* __restrict__ out)
{
    int c = blockIdx.x * blockDim.x + threadIdx.x;
    if (c >= Dq) return;
    float s = 0.f, ss = 0.f;
    for (int bb = 0; bb < Bq; bb++) {
        float v = fid[bb*Dq + c]; s += v; ss += v*v;
    }
    float m = s / (float)Bq;
    float var = ss / (float)Bq - m*m;
    float rs = rsqrtf(var + EPSq);
    for (int bb = 0; bb < Bq; bb++)
        out[bb*Dq + c] = (fid[bb*Dq + c] - m) * rs * g[c] + b[c];
}

// ---------------- host ----------------
#define GETSYM(p, s) { void* _t; cudaGetSymbolAddress(&_t, s); p = (float*)_t; }

static inline void launch_gemm(const float* A, int lda, const float* W, float* C,
                               int Nc, int K)
{
    dim3 grid((Nc + 127) / 128, Nq / 128);
    gemm_tc<<<grid, 256>>>(A, lda, W, C, Nc, K);
}

extern "C" void kernel_launch(void* const* d_in, const int* in_sizes, int n_in,
                              void* d_out, int out_size)
{
    const float* x        = (const float*)d_in[0];
    const float* sq_w     = (const float*)d_in[1];
    const float* sq_bn_g  = (const float*)d_in[2];
    const float* sq_bn_b  = (const float*)d_in[3];
    const float* dw_w     = (const float*)d_in[4];
    const float* dw_bn_g  = (const float*)d_in[5];
    const float* dw_bn_b  = (const float*)d_in[6];
    const float* ex_w     = (const float*)d_in[7];
    const float* ex_bn_g  = (const float*)d_in[8];
    const float* ex_bn_b  = (const float*)d_in[9];
    const float* attr_g   = (const float*)d_in[10];
    const float* attr_b   = (const float*)d_in[11];
    const float* mnorm_g  = (const float*)d_in[12];
    const float* mnorm_b  = (const float*)d_in[13];
    const float* in_proj_w= (const float*)d_in[14];
    const float* conv_w   = (const float*)d_in[15];
    const float* conv_b   = (const float*)d_in[16];
    const float* xproj_w  = (const float*)d_in[17];
    const float* dtproj_w = (const float*)d_in[18];
    const float* dtproj_b = (const float*)d_in[19];
    const float* A_log    = (const float*)d_in[20];
    const float* D_param  = (const float*)d_in[21];
    const float* out_proj_w = (const float*)d_in[22];
    const float* gate_w   = (const float*)d_in[23];
    const float* gate_b   = (const float*)d_in[24];
    const float* idn_g    = (const float*)d_in[25];
    const float* idn_b    = (const float*)d_in[26];
    const float* idbn_g   = (const float*)d_in[27];
    const float* idbn_b   = (const float*)d_in[28];
    float* out = (float*)d_out;

    float *h0,*tmpH,*h2,*e,*x1,*xn,*xz,*xm2,*dbc,*del,*y,*mo,*gl,*xf;
    float *rm,*rs,*rm2,*rs2,*sum,*sq,*fid;
    GETSYM(h0, g_h0);   GETSYM(tmpH, g_tmpH); GETSYM(h2, g_h2);
    GETSYM(e, g_e);     GETSYM(x1, g_x1);     GETSYM(xn, g_xn);
    GETSYM(xz, g_xz);   GETSYM(xm2, g_xm2);   GETSYM(dbc, g_dbc);
    GETSYM(del, g_del); GETSYM(y, g_y);       GETSYM(mo, g_mo);
    GETSYM(gl, g_gl);   GETSYM(xf, g_xf);
    GETSYM(rm, g_rm);   GETSYM(rs, g_rs);     GETSYM(rm2, g_rm2); GETSYM(rs2, g_rs2);
    GETSYM(sum, g_sum); GETSYM(sq, g_sq);     GETSYM(fid, g_fid);

    const int T = 256;
    dim3 gHID((Nq*HIDq + T-1)/T), gD((Nq*Dq + T-1)/T), gDI((Nq*DIq + T-1)/T);

    // 1) squeeze: h0 = x @ sq_w^T ; BN+SiLU
    launch_gemm(x, Dq, sq_w, h0, HIDq, Dq);
    cudaMemsetAsync(sum, 0, HIDq*sizeof(float));
    cudaMemsetAsync(sq,  0, HIDq*sizeof(float));
    bn_stats<<<dim3(32,1), T>>>(h0, Nq, HIDq, sum, sq);
    bn_silu<<<gHID, T>>>(h0, h0, sum, sq, sq_bn_g, sq_bn_b, Nq, HIDq);

    // 2) dwconv K=5 ; BN+SiLU
    dwconv5<<<gHID, T>>>(h0, dw_w, tmpH);
    cudaMemsetAsync(sum, 0, HIDq*sizeof(float));
    cudaMemsetAsync(sq,  0, HIDq*sizeof(float));
    bn_stats<<<dim3(32,1), T>>>(tmpH, Nq, HIDq, sum, sq);
    bn_silu<<<gHID, T>>>(tmpH, h2, sum, sq, dw_bn_g, dw_bn_b, Nq, HIDq);

    // 3) excite: e = h2 @ ex_w^T ; x1 = x + BN(e)
    launch_gemm(h2, HIDq, ex_w, e, Dq, HIDq);
    cudaMemsetAsync(sum, 0, Dq*sizeof(float));
    cudaMemsetAsync(sq,  0, Dq*sizeof(float));
    bn_stats<<<dim3(32,3), T>>>(e, Nq, Dq, sum, sq);
    bn_add<<<gD, T>>>(e, x, x1, sum, sq, ex_bn_g, ex_bn_b, Nq, Dq);

    // 4) LN stats of x1; feat_attr; xn
    row_stats<<<Nq, T>>>(x1, rm, rs, Dq);
    attr_max<<<dim3(Bq,3), T>>>(x1, rm, rs, attr_g, attr_b, out);
    ln_apply<<<gD, T>>>(x1, rm, rs, mnorm_g, mnorm_b, xn, Dq);

    // 5) Mamba in_proj
    launch_gemm(xn, Dq, in_proj_w, xz, 2*DIq, Dq);

    // 6) causal conv + silu -> xm2
    conv_causal_silu<<<gDI, T>>>(xz, conv_w, conv_b, xm2);

    // 7) x_proj -> dbc ; dt_proj -> delta ; softplus
    launch_gemm(xm2, DIq, xproj_w, dbc, 80, DIq);
    launch_gemm(dbc, 80, dtproj_w, del, DIq, DTRq);
    softplus_bias<<<gDI, T>>>(del, dtproj_b);

    // 8) selective scan (fused +u*D and *silu(z))
    scan_k<<<dim3(DIq/256, Bq), 256>>>(del, xm2, dbc, xz, A_log, D_param, y);

    // 9) out_proj, gate, combine
    launch_gemm(y, DIq, out_proj_w, mo, Dq, DIq);
    launch_gemm(xn, Dq, gate_w, gl, Dq, Dq);
    combine<<<gD, T>>>(x, x1, mo, gl, gate_b, xf);

    // 10) feat_id + feat_id_bn
    row_stats<<<Nq, T>>>(xf, rm2, rs2, Dq);
    feat_id_k<<<dim3(Bq,3), T>>>(xf, rm2, rs2, idn_g, idn_b, fid, out + Bq*Dq);
    feat_bn<<<3, T>>>(fid, idbn_g, idbn_b, out + 2*Bq*Dq);
}